// round 10
// baseline (speedup 1.0000x reference)
#include <cuda_runtime.h>
#include <cuda_bf16.h>
#include <math.h>

#define H 512
#define W 512
#define WPR 16                 // 32-bit words per row
#define GRID 128               // blocks: 4 rows each, phase 1 + phase 2
#define MISS (1 << 20)

// Scratch (allocation-free rule: __device__ globals)
// RAW (pre-erosion) row-packed masks: bit b of d_rawA[r*16+w] = pred!=0 at (r, w*32+b).
__device__ unsigned d_rawA[H * WPR];
__device__ unsigned d_rawB[H * WPR];
__device__ float d_blkNum[GRID];
__device__ float d_blkDen[GRID];
__device__ unsigned d_cnt;             // zero-init; atomicInc wraps -> reset
__device__ unsigned d_bar;             // grid barrier; reset by final block

// ---------------------------------------------------------------------------
// Surface word computed on the fly from global raw words (cold path only).
// ---------------------------------------------------------------------------
__device__ __noinline__ unsigned sur_word_g(const unsigned* __restrict__ raw,
                                            int r, int w) {
    if (r < 0 || r >= H || w < 0 || w >= WPR) return 0u;
    unsigned cen = raw[r * WPR + w];
    unsigned up = (r > 0)     ? raw[(r - 1) * WPR + w] : 0u;
    unsigned dn = (r < H - 1) ? raw[(r + 1) * WPR + w] : 0u;
    unsigned lw = (w > 0)     ? raw[r * WPR + w - 1] : 0u;
    unsigned rw = (w < WPR-1) ? raw[r * WPR + w + 1] : 0u;
    unsigned lm = (cen << 1) | (lw >> 31);
    unsigned rm = (cen >> 1) | (rw << 31);
    return cen & ~(up & dn & lm & rm);
}

// Cold exact per-pixel search on raw global masks (probability ~4e-5 per run).
__device__ __noinline__ float search_fb(const unsigned* __restrict__ raw,
                                        int r, int w, int bit) {
    float best = 1e12f;
    for (int dr = 0; dr < H; ++dr) {
        int dr2 = dr * dr;
        if ((float)dr2 >= best) break;
        #pragma unroll
        for (int sgn = 0; sgn < 2; ++sgn) {
            if (sgn == 1 && dr == 0) continue;
            int gr = sgn ? (r + dr) : (r - dr);
            if (gr < 0 || gr >= H) continue;
            unsigned lo = sur_word_g(raw, gr, w - 1);
            unsigned mi = sur_word_g(raw, gr, w);
            unsigned hi = sur_word_g(raw, gr, w + 1);
            unsigned long long up =
                (((unsigned long long)(mi & (0xFFFFFFFFu >> (31 - bit)))) << 32) |
                (unsigned long long)lo;
            unsigned long long dn =
                (((unsigned long long)hi) << (32 - bit)) |
                (unsigned long long)(mi >> bit);
            int dl = up ? (bit + 32) - (63 - __clzll(up)) : MISS;
            int drr = dn ? (__ffsll((long long)dn) - 1)   : MISS;
            int dc = min(dl, drr);
            if (dc <= 32) {
                best = fminf(best, (float)(dr2 + dc * dc));
            } else if ((float)(dr2 + 1024) < best) {
                int dfl = MISS, dfr = MISS;
                for (int ww = w - 2; ww >= 0; --ww) {
                    unsigned x = sur_word_g(raw, gr, ww);
                    if (x) { dfl = (w - ww) * 32 + bit - (31 - __clz(x)); break; }
                }
                for (int ww = w + 2; ww < WPR; ++ww) {
                    unsigned x = sur_word_g(raw, gr, ww);
                    if (x) { dfr = (ww - w) * 32 - bit + (__ffs(x) - 1); break; }
                }
                int dm = min(min(dfl, dfr), dc);
                if (dm < MISS)
                    best = fminf(best, (float)(dr2 + dm * dm));
            }
        }
    }
    return sqrtf(best);
}

// ===========================================================================
// Single persistent kernel, GRID=128 blocks x 512 threads (1 block/SM, safe).
// Phase 1: block b packs RAW rows 4b..4b+3 (2 LDG per pixel).
// Barrier. Phase 2: stage raw rows 4b-4..4b+7, erode in shared, per-word
// ball-dilation counting, deterministic fold.
// ===========================================================================
__global__ void __launch_bounds__(512) k_all(const float* __restrict__ pred,
                                             const float* __restrict__ gt,
                                             float* __restrict__ out) {
    __shared__ unsigned sraw[2][12][WPR];   // raw rows gb-4..gb+7
    __shared__ unsigned stg[2][10][18];     // surface rows gb-3..gb+6, padded
    __shared__ float wNum[16], wDen[16];
    __shared__ bool  isLast;

    const int c = threadIdx.x;
    const int lane = c & 31;
    const int wwarp = c >> 5;               // warp id == word index
    const int gb = blockIdx.x * 4;

    // ===================== Phase 1: pack raw rows gb..gb+3 =====================
    {
        float pv[4], gv[4];
        #pragma unroll
        for (int k = 0; k < 4; ++k) {
            pv[k] = pred[(gb + k) * W + c];
            gv[k] = gt[(gb + k) * W + c];
        }
        #pragma unroll
        for (int k = 0; k < 4; ++k) {
            unsigned ba = __ballot_sync(0xFFFFFFFFu, pv[k] != 0.0f);
            unsigned bb = __ballot_sync(0xFFFFFFFFu, gv[k] != 0.0f);
            if (lane == 0) {
                d_rawA[(gb + k) * WPR + wwarp] = ba;
                d_rawB[(gb + k) * WPR + wwarp] = bb;
            }
        }
    }

    // ===================== Grid barrier (128 arrivals) =====================
    __syncthreads();
    if (c == 0) {
        __threadfence();
        unsigned arrived = atomicAdd(&d_bar, 1u) + 1u;
        if (arrived < GRID) {
            while (atomicAdd(&d_bar, 0u) < GRID) { __nanosleep(32); }
        }
        __threadfence();
    }
    __syncthreads();

    // ===================== Phase 2: stage raw + erode in shared =====================
    if (c < 384) {
        int f = c / 192, rest = c % 192;
        int rr = rest >> 4, ww = rest & 15;       // rr 0..11
        int gr = gb - 4 + rr;
        bool ok = (gr >= 0) && (gr < H);
        sraw[f][rr][ww] = ok ? (f ? d_rawB : d_rawA)[gr * WPR + ww] : 0u;
    }
    __syncthreads();

    if (c < 320) {
        int f = c / 160, rest = c % 160;
        int rr = rest >> 4, ww = rest & 15;       // rr 0..9 -> row gb-3+rr
        int ri = rr + 1;
        unsigned cen = sraw[f][ri][ww];
        unsigned up = sraw[f][ri - 1][ww];
        unsigned dn = sraw[f][ri + 1][ww];
        unsigned lw = (ww > 0)  ? sraw[f][ri][ww - 1] : 0u;
        unsigned rw = (ww < 15) ? sraw[f][ri][ww + 1] : 0u;
        unsigned lm = (cen << 1) | (lw >> 31);
        unsigned rm = (cen >> 1) | (rw << 31);
        stg[f][rr][ww + 1] = cen & ~(up & dn & lm & rm);
    } else if (c < 360) {
        int idx = c - 320;                        // 40 pad words -> 0
        int f = idx / 20, rest = idx % 20;
        stg[f][rest >> 1][(rest & 1) ? 17 : 0] = 0u;
    }
    __syncthreads();

    // ===================== Phase 2: per-word counting =====================
    float num = 0.0f;
    float den = 0.0f;

    if (c < 128) {
        const int f = c >> 6;            // dilated (source) feature
        const int local = c & 63;
        const int rloc = local >> 4;     // 0..3
        const int w = local & 15;
        const int gr = gb + rloc;

        unsigned a0c0, a0c1, a0c2, a0c3;
        unsigned a1c0 = 0, a1c1 = 0, a1c2 = 0, a1c3 = 0;
        unsigned a2c0 = 0, a2c1 = 0, a2c2 = 0;
        unsigned a3c0 = 0, a3c1 = 0;

        #pragma unroll
        for (int dr = -3; dr <= 3; ++dr) {
            const unsigned* row = &stg[f][rloc + 3 + dr][0];
            unsigned lo = row[w], mi = row[w + 1], hi = row[w + 2];
            unsigned c0 = mi;
            unsigned c1 = __funnelshift_r(mi, hi, 1) | __funnelshift_l(lo, mi, 1);
            const int adr = (dr < 0) ? -dr : dr;
            if (adr == 0) {
                a0c0 = c0; a0c1 = c1;
                a0c2 = __funnelshift_r(mi, hi, 2) | __funnelshift_l(lo, mi, 2);
                a0c3 = __funnelshift_r(mi, hi, 3) | __funnelshift_l(lo, mi, 3);
            } else if (adr == 1) {
                a1c0 |= c0; a1c1 |= c1;
                a1c2 |= __funnelshift_r(mi, hi, 2) | __funnelshift_l(lo, mi, 2);
                a1c3 |= __funnelshift_r(mi, hi, 3) | __funnelshift_l(lo, mi, 3);
            } else if (adr == 2) {
                a2c0 |= c0; a2c1 |= c1;
                a2c2 |= __funnelshift_r(mi, hi, 2) | __funnelshift_l(lo, mi, 2);
            } else {
                a3c0 |= c0; a3c1 |= c1;
            }
        }

        const unsigned tgt = stg[f ^ 1][rloc + 3][w + 1];
        den = (float)__popc(tgt);

        // incremental ball dilations: d^2 = 0,1,2,4,5,8,9,10
        unsigned D = a0c0, Dn;
        Dn = D | a0c1 | a1c0; num += 1.0f        * (float)__popc(tgt & Dn & ~D); D = Dn;
        Dn = D | a1c1;        num += 1.41421356f * (float)__popc(tgt & Dn & ~D); D = Dn;
        Dn = D | a0c2 | a2c0; num += 2.0f        * (float)__popc(tgt & Dn & ~D); D = Dn;
        Dn = D | a1c2 | a2c1; num += 2.23606798f * (float)__popc(tgt & Dn & ~D); D = Dn;
        Dn = D | a2c2;        num += 2.82842712f * (float)__popc(tgt & Dn & ~D); D = Dn;
        Dn = D | a0c3 | a3c0; num += 3.0f        * (float)__popc(tgt & Dn & ~D); D = Dn;
        Dn = D | a1c3 | a3c1; num += 3.16227766f * (float)__popc(tgt & Dn & ~D); D = Dn;

        // cold exact fallback for pixels with d^2 > 10
        unsigned rem = tgt & ~D;
        while (rem) {
            int bt = __ffs(rem) - 1;
            rem &= rem - 1u;
            num += search_fb(f ? d_rawB : d_rawA, gr, w, bt);
        }
    }

    // ===================== deterministic reduction =====================
    #pragma unroll
    for (int off = 16; off > 0; off >>= 1) {
        num += __shfl_down_sync(0xFFFFFFFFu, num, off);
        den += __shfl_down_sync(0xFFFFFFFFu, den, off);
    }
    if (lane == 0) { wNum[wwarp] = num; wDen[wwarp] = den; }
    __syncthreads();

    if (wwarp == 0) {
        float n = (lane < 16) ? wNum[lane] : 0.0f;
        float d = (lane < 16) ? wDen[lane] : 0.0f;
        #pragma unroll
        for (int off = 8; off > 0; off >>= 1) {
            n += __shfl_down_sync(0xFFFFFFFFu, n, off);
            d += __shfl_down_sync(0xFFFFFFFFu, d, off);
        }
        if (lane == 0) {
            d_blkNum[blockIdx.x] = n;
            d_blkDen[blockIdx.x] = d;
            __threadfence();
            unsigned old = atomicInc(&d_cnt, GRID - 1);  // wraps -> self-reset
            isLast = (old == GRID - 1);
        }
    }
    __syncthreads();

    if (isLast) {
        float n = (c < GRID) ? d_blkNum[c] : 0.0f;
        float d = (c < GRID) ? d_blkDen[c] : 0.0f;
        #pragma unroll
        for (int off = 16; off > 0; off >>= 1) {
            n += __shfl_down_sync(0xFFFFFFFFu, n, off);
            d += __shfl_down_sync(0xFFFFFFFFu, d, off);
        }
        if (lane == 0) { wNum[wwarp] = n; wDen[wwarp] = d; }
        __syncthreads();
        if (wwarp == 0) {
            float nn = (lane < 16) ? wNum[lane] : 0.0f;
            float dd = (lane < 16) ? wDen[lane] : 0.0f;
            #pragma unroll
            for (int off = 8; off > 0; off >>= 1) {
                nn += __shfl_down_sync(0xFFFFFFFFu, nn, off);
                dd += __shfl_down_sync(0xFFFFFFFFu, dd, off);
            }
            if (lane == 0) {
                out[0] = nn / dd;
                d_bar = 0u;     // all blocks already passed the barrier
            }
        }
    }
}

extern "C" void kernel_launch(void* const* d_in, const int* in_sizes, int n_in,
                              void* d_out, int out_size) {
    const float* pred = (const float*)d_in[0];
    const float* gt   = (const float*)d_in[1];
    float* out = (float*)d_out;

    k_all<<<GRID, 512>>>(pred, gt, out);
}

// round 11
// speedup vs baseline: 1.2043x; 1.2043x over previous
#include <cuda_runtime.h>
#include <cuda_bf16.h>
#include <math.h>

#define H 512
#define W 512
#define WPR 16                 // 32-bit words per row
#define GRID 128               // 4 rows per block, fully self-contained
#define MISS (1 << 20)

// Scratch (allocation-free rule: __device__ globals)
__device__ float d_blkNum[GRID];
__device__ float d_blkDen[GRID];
__device__ unsigned d_cnt;     // zero-init; atomicInc wraps -> self-resetting

// ---------------------------------------------------------------------------
// Cold path: recompute raw/surface mask words directly from float inputs.
// Only used for pixels with nearest surface distance^2 > 10 (P ~ 4e-5 / run).
// ---------------------------------------------------------------------------
__device__ __noinline__ unsigned raw_word_f(const float* __restrict__ src,
                                            int r, int w) {
    if (r < 0 || r >= H) return 0u;
    const float* p = src + r * W + w * 32;
    unsigned x = 0;
    for (int j = 0; j < 32; ++j)
        if (p[j] != 0.0f) x |= 1u << j;
    return x;
}

__device__ __noinline__ unsigned sur_word_f(const float* __restrict__ src,
                                            int r, int w) {
    if (r < 0 || r >= H || w < 0 || w >= WPR) return 0u;
    unsigned cen = raw_word_f(src, r, w);
    unsigned up  = raw_word_f(src, r - 1, w);
    unsigned dn  = raw_word_f(src, r + 1, w);
    unsigned lb  = (w > 0)  ? ((raw_word_f(src, r, w - 1) >> 31) & 1u) : 0u;
    unsigned rb  = (w < 15) ? (raw_word_f(src, r, w + 1) & 1u) : 0u;
    unsigned lm = (cen << 1) | lb;
    unsigned rm = (cen >> 1) | (rb << 31);
    return cen & ~(up & dn & lm & rm);
}

__device__ __noinline__ float search_fb(const float* __restrict__ src,
                                        int r, int w, int bit) {
    float best = 1e12f;
    for (int dr = 0; dr < H; ++dr) {
        int dr2 = dr * dr;
        if ((float)dr2 >= best) break;
        for (int sgn = 0; sgn < 2; ++sgn) {
            if (sgn == 1 && dr == 0) continue;
            int gr = sgn ? (r + dr) : (r - dr);
            if (gr < 0 || gr >= H) continue;
            unsigned lo = sur_word_f(src, gr, w - 1);
            unsigned mi = sur_word_f(src, gr, w);
            unsigned hi = sur_word_f(src, gr, w + 1);
            unsigned long long up =
                (((unsigned long long)(mi & (0xFFFFFFFFu >> (31 - bit)))) << 32) |
                (unsigned long long)lo;
            unsigned long long dn =
                (((unsigned long long)hi) << (32 - bit)) |
                (unsigned long long)(mi >> bit);
            int dl = up ? (bit + 32) - (63 - __clzll(up)) : MISS;
            int drr = dn ? (__ffsll((long long)dn) - 1)   : MISS;
            int dc = min(dl, drr);
            if (dc <= 32) {
                best = fminf(best, (float)(dr2 + dc * dc));
            } else if ((float)(dr2 + 1024) < best) {
                int dfl = MISS, dfr = MISS;
                for (int ww = w - 2; ww >= 0; --ww) {
                    unsigned x = sur_word_f(src, gr, ww);
                    if (x) { dfl = (w - ww) * 32 + bit - (31 - __clz(x)); break; }
                }
                for (int ww = w + 2; ww < WPR; ++ww) {
                    unsigned x = sur_word_f(src, gr, ww);
                    if (x) { dfr = (ww - w) * 32 - bit + (__ffs(x) - 1); break; }
                }
                int dm = min(min(dfl, dfr), dc);
                if (dm < MISS)
                    best = fminf(best, (float)(dr2 + dm * dm));
            }
        }
    }
    return sqrtf(best);
}

// ===========================================================================
// Single kernel, NO grid barrier. Block b is fully self-contained:
//   load pred/gt rows 4b-4 .. 4b+7 -> ballot-pack raw words in shared
//   -> bitwise erosion (surface rows 4b-3 .. 4b+6) -> per-word ball-dilation
//   counting for rows 4b..4b+3 -> deterministic fold via last-block pattern.
// ===========================================================================
__global__ void __launch_bounds__(512) k_all(const float* __restrict__ pred,
                                             const float* __restrict__ gt,
                                             float* __restrict__ out) {
    __shared__ unsigned sraw[2][12][WPR];   // raw rows gb-4..gb+7
    __shared__ unsigned stg[2][10][18];     // surface rows gb-3..gb+6, padded
    __shared__ float wNum[16], wDen[16];
    __shared__ bool  isLast;

    const int c = threadIdx.x;
    const int lane = c & 31;
    const int wwarp = c >> 5;               // warp id == word index
    const int gb = blockIdx.x * 4;

    // ---- load 12 rows of both features (24 independent coalesced LDGs) ----
    float pv[12], gv[12];
    #pragma unroll
    for (int rr = 0; rr < 12; ++rr) {
        int gr = gb - 4 + rr;
        bool ok = (gr >= 0) && (gr < H);
        pv[rr] = ok ? pred[gr * W + c] : 0.0f;
        gv[rr] = ok ? gt[gr * W + c]   : 0.0f;
    }
    #pragma unroll
    for (int rr = 0; rr < 12; ++rr) {
        unsigned ba = __ballot_sync(0xFFFFFFFFu, pv[rr] != 0.0f);
        unsigned bb = __ballot_sync(0xFFFFFFFFu, gv[rr] != 0.0f);
        if (lane == 0) { sraw[0][rr][wwarp] = ba; sraw[1][rr][wwarp] = bb; }
    }
    __syncthreads();

    // ---- bitwise erosion -> padded surface rows ----
    if (c < 320) {
        int f = c / 160, rest = c % 160;
        int rr = rest >> 4, ww = rest & 15;   // rr 0..9 -> surface row gb-3+rr
        int ri = rr + 1;                      // center raw row index
        unsigned cen = sraw[f][ri][ww];
        unsigned up = sraw[f][ri - 1][ww];
        unsigned dn = sraw[f][ri + 1][ww];
        unsigned lw = (ww > 0)  ? sraw[f][ri][ww - 1] : 0u;
        unsigned rw = (ww < 15) ? sraw[f][ri][ww + 1] : 0u;
        unsigned lm = (cen << 1) | (lw >> 31);
        unsigned rm = (cen >> 1) | (rw << 31);
        stg[f][rr][ww + 1] = cen & ~(up & dn & lm & rm);
    } else if (c < 360) {
        int idx = c - 320;                    // 40 pad words -> 0
        int f = idx / 20, rest = idx % 20;
        stg[f][rest >> 1][(rest & 1) ? 17 : 0] = 0u;
    }
    __syncthreads();

    // ---- per-word ball-dilation counting ----
    float num = 0.0f;
    float den = 0.0f;

    if (c < 128) {
        const int f = c >> 6;            // dilated (source) feature
        const int local = c & 63;
        const int rloc = local >> 4;     // 0..3
        const int w = local & 15;
        const int gr = gb + rloc;

        unsigned a0c0, a0c1, a0c2, a0c3;
        unsigned a1c0 = 0, a1c1 = 0, a1c2 = 0, a1c3 = 0;
        unsigned a2c0 = 0, a2c1 = 0, a2c2 = 0;
        unsigned a3c0 = 0, a3c1 = 0;

        #pragma unroll
        for (int dr = -3; dr <= 3; ++dr) {
            const unsigned* row = &stg[f][rloc + 3 + dr][0];
            unsigned lo = row[w], mi = row[w + 1], hi = row[w + 2];
            unsigned c0 = mi;
            unsigned c1 = __funnelshift_r(mi, hi, 1) | __funnelshift_l(lo, mi, 1);
            const int adr = (dr < 0) ? -dr : dr;
            if (adr == 0) {
                a0c0 = c0; a0c1 = c1;
                a0c2 = __funnelshift_r(mi, hi, 2) | __funnelshift_l(lo, mi, 2);
                a0c3 = __funnelshift_r(mi, hi, 3) | __funnelshift_l(lo, mi, 3);
            } else if (adr == 1) {
                a1c0 |= c0; a1c1 |= c1;
                a1c2 |= __funnelshift_r(mi, hi, 2) | __funnelshift_l(lo, mi, 2);
                a1c3 |= __funnelshift_r(mi, hi, 3) | __funnelshift_l(lo, mi, 3);
            } else if (adr == 2) {
                a2c0 |= c0; a2c1 |= c1;
                a2c2 |= __funnelshift_r(mi, hi, 2) | __funnelshift_l(lo, mi, 2);
            } else {
                a3c0 |= c0; a3c1 |= c1;
            }
        }

        const unsigned tgt = stg[f ^ 1][rloc + 3][w + 1];
        den = (float)__popc(tgt);

        // incremental ball dilations: d^2 = 0,1,2,4,5,8,9,10
        unsigned D = a0c0, Dn;
        Dn = D | a0c1 | a1c0; num += 1.0f        * (float)__popc(tgt & Dn & ~D); D = Dn;
        Dn = D | a1c1;        num += 1.41421356f * (float)__popc(tgt & Dn & ~D); D = Dn;
        Dn = D | a0c2 | a2c0; num += 2.0f        * (float)__popc(tgt & Dn & ~D); D = Dn;
        Dn = D | a1c2 | a2c1; num += 2.23606798f * (float)__popc(tgt & Dn & ~D); D = Dn;
        Dn = D | a2c2;        num += 2.82842712f * (float)__popc(tgt & Dn & ~D); D = Dn;
        Dn = D | a0c3 | a3c0; num += 3.0f        * (float)__popc(tgt & Dn & ~D); D = Dn;
        Dn = D | a1c3 | a3c1; num += 3.16227766f * (float)__popc(tgt & Dn & ~D); D = Dn;

        // cold exact fallback (recomputes masks straight from float inputs)
        unsigned rem = tgt & ~D;
        while (rem) {
            int bt = __ffs(rem) - 1;
            rem &= rem - 1u;
            num += search_fb(f ? gt : pred, gr, w, bt);
        }
    }

    // ---- deterministic reduction + last-block fold ----
    #pragma unroll
    for (int off = 16; off > 0; off >>= 1) {
        num += __shfl_down_sync(0xFFFFFFFFu, num, off);
        den += __shfl_down_sync(0xFFFFFFFFu, den, off);
    }
    if (lane == 0) { wNum[wwarp] = num; wDen[wwarp] = den; }
    __syncthreads();

    if (wwarp == 0) {
        float n = (lane < 16) ? wNum[lane] : 0.0f;
        float d = (lane < 16) ? wDen[lane] : 0.0f;
        #pragma unroll
        for (int off = 8; off > 0; off >>= 1) {
            n += __shfl_down_sync(0xFFFFFFFFu, n, off);
            d += __shfl_down_sync(0xFFFFFFFFu, d, off);
        }
        if (lane == 0) {
            d_blkNum[blockIdx.x] = n;
            d_blkDen[blockIdx.x] = d;
            __threadfence();
            unsigned old = atomicInc(&d_cnt, GRID - 1);  // wraps -> self-reset
            isLast = (old == GRID - 1);
        }
    }
    __syncthreads();

    if (isLast) {
        float n = (c < GRID) ? d_blkNum[c] : 0.0f;
        float d = (c < GRID) ? d_blkDen[c] : 0.0f;
        #pragma unroll
        for (int off = 16; off > 0; off >>= 1) {
            n += __shfl_down_sync(0xFFFFFFFFu, n, off);
            d += __shfl_down_sync(0xFFFFFFFFu, d, off);
        }
        if (lane == 0) { wNum[wwarp] = n; wDen[wwarp] = d; }
        __syncthreads();
        if (wwarp == 0) {
            float nn = (lane < 16) ? wNum[lane] : 0.0f;
            float dd = (lane < 16) ? wDen[lane] : 0.0f;
            #pragma unroll
            for (int off = 8; off > 0; off >>= 1) {
                nn += __shfl_down_sync(0xFFFFFFFFu, nn, off);
                dd += __shfl_down_sync(0xFFFFFFFFu, dd, off);
            }
            if (lane == 0) out[0] = nn / dd;
        }
    }
}

extern "C" void kernel_launch(void* const* d_in, const int* in_sizes, int n_in,
                              void* d_out, int out_size) {
    const float* pred = (const float*)d_in[0];
    const float* gt   = (const float*)d_in[1];
    float* out = (float*)d_out;

    k_all<<<GRID, 512>>>(pred, gt, out);
}

// round 12
// speedup vs baseline: 1.2399x; 1.0295x over previous
#include <cuda_runtime.h>
#include <cuda_bf16.h>
#include <math.h>

#define H 512
#define W 512
#define WPR 16                 // 32-bit words per row
#define GRID 256               // 2 rows per block, fully self-contained
#define MISS (1 << 20)

// Scratch (allocation-free rule: __device__ globals)
__device__ float d_blkNum[GRID];
__device__ float d_blkDen[GRID];
__device__ unsigned d_cnt;     // zero-init; atomicInc wraps -> self-resetting

// ---------------------------------------------------------------------------
// Cold path: recompute raw/surface mask words directly from float inputs.
// Only used for pixels with nearest surface distance^2 > 10 (P ~ 3e-5 / run).
// ---------------------------------------------------------------------------
__device__ __noinline__ unsigned raw_word_f(const float* __restrict__ src,
                                            int r, int w) {
    if (r < 0 || r >= H) return 0u;
    const float* p = src + r * W + w * 32;
    unsigned x = 0;
    for (int j = 0; j < 32; ++j)
        if (p[j] != 0.0f) x |= 1u << j;
    return x;
}

__device__ __noinline__ unsigned sur_word_f(const float* __restrict__ src,
                                            int r, int w) {
    if (r < 0 || r >= H || w < 0 || w >= WPR) return 0u;
    unsigned cen = raw_word_f(src, r, w);
    unsigned up  = raw_word_f(src, r - 1, w);
    unsigned dn  = raw_word_f(src, r + 1, w);
    unsigned lb  = (w > 0)  ? ((raw_word_f(src, r, w - 1) >> 31) & 1u) : 0u;
    unsigned rb  = (w < 15) ? (raw_word_f(src, r, w + 1) & 1u) : 0u;
    unsigned lm = (cen << 1) | lb;
    unsigned rm = (cen >> 1) | (rb << 31);
    return cen & ~(up & dn & lm & rm);
}

__device__ __noinline__ float search_fb(const float* __restrict__ src,
                                        int r, int w, int bit) {
    float best = 1e12f;
    for (int dr = 0; dr < H; ++dr) {
        int dr2 = dr * dr;
        if ((float)dr2 >= best) break;
        for (int sgn = 0; sgn < 2; ++sgn) {
            if (sgn == 1 && dr == 0) continue;
            int gr = sgn ? (r + dr) : (r - dr);
            if (gr < 0 || gr >= H) continue;
            unsigned lo = sur_word_f(src, gr, w - 1);
            unsigned mi = sur_word_f(src, gr, w);
            unsigned hi = sur_word_f(src, gr, w + 1);
            unsigned long long up =
                (((unsigned long long)(mi & (0xFFFFFFFFu >> (31 - bit)))) << 32) |
                (unsigned long long)lo;
            unsigned long long dn =
                (((unsigned long long)hi) << (32 - bit)) |
                (unsigned long long)(mi >> bit);
            int dl = up ? (bit + 32) - (63 - __clzll(up)) : MISS;
            int drr = dn ? (__ffsll((long long)dn) - 1)   : MISS;
            int dc = min(dl, drr);
            if (dc <= 32) {
                best = fminf(best, (float)(dr2 + dc * dc));
            } else if ((float)(dr2 + 1024) < best) {
                int dfl = MISS, dfr = MISS;
                for (int ww = w - 2; ww >= 0; --ww) {
                    unsigned x = sur_word_f(src, gr, ww);
                    if (x) { dfl = (w - ww) * 32 + bit - (31 - __clz(x)); break; }
                }
                for (int ww = w + 2; ww < WPR; ++ww) {
                    unsigned x = sur_word_f(src, gr, ww);
                    if (x) { dfr = (ww - w) * 32 - bit + (__ffs(x) - 1); break; }
                }
                int dm = min(min(dfl, dfr), dc);
                if (dm < MISS)
                    best = fminf(best, (float)(dr2 + dm * dm));
            }
        }
    }
    return sqrtf(best);
}

// ===========================================================================
// Single kernel, no grid barrier. Block b handles rows 2b, 2b+1:
//   load pred/gt rows 2b-4..2b+5 -> ballot-pack raw words in shared
//   -> bitwise erosion (surface rows 2b-3..2b+4) -> per-word ball-dilation
//   counting -> deterministic fold via last-block pattern.
// ===========================================================================
__global__ void __launch_bounds__(512, 2) k_all(const float* __restrict__ pred,
                                                const float* __restrict__ gt,
                                                float* __restrict__ out) {
    __shared__ unsigned sraw[2][10][WPR];   // raw rows gb-4..gb+5
    __shared__ unsigned stg[2][8][18];      // surface rows gb-3..gb+4, padded
    __shared__ float wNum[16], wDen[16];
    __shared__ bool  isLast;

    const int c = threadIdx.x;
    const int lane = c & 31;
    const int wwarp = c >> 5;               // warp id == word index
    const int gb = blockIdx.x * 2;

    // ---- load 10 rows of both features (20 independent coalesced LDGs) ----
    float pv[10], gv[10];
    #pragma unroll
    for (int rr = 0; rr < 10; ++rr) {
        int gr = gb - 4 + rr;
        bool ok = (gr >= 0) && (gr < H);
        pv[rr] = ok ? pred[gr * W + c] : 0.0f;
        gv[rr] = ok ? gt[gr * W + c]   : 0.0f;
    }
    #pragma unroll
    for (int rr = 0; rr < 10; ++rr) {
        unsigned ba = __ballot_sync(0xFFFFFFFFu, pv[rr] != 0.0f);
        unsigned bb = __ballot_sync(0xFFFFFFFFu, gv[rr] != 0.0f);
        if (lane == 0) { sraw[0][rr][wwarp] = ba; sraw[1][rr][wwarp] = bb; }
    }
    __syncthreads();

    // ---- bitwise erosion -> padded surface rows (8 rows x 16 words x 2) ----
    if (c < 256) {
        int f = c >> 7, rest = c & 127;
        int rr = rest >> 4, ww = rest & 15;   // rr 0..7 -> surface row gb-3+rr
        int ri = rr + 1;                      // center raw row index
        unsigned cen = sraw[f][ri][ww];
        unsigned up = sraw[f][ri - 1][ww];
        unsigned dn = sraw[f][ri + 1][ww];
        unsigned lw = (ww > 0)  ? sraw[f][ri][ww - 1] : 0u;
        unsigned rw = (ww < 15) ? sraw[f][ri][ww + 1] : 0u;
        unsigned lm = (cen << 1) | (lw >> 31);
        unsigned rm = (cen >> 1) | (rw << 31);
        stg[f][rr][ww + 1] = cen & ~(up & dn & lm & rm);
    } else if (c < 288) {
        int idx = c - 256;                    // 32 pad words -> 0
        int f = idx >> 4, rest = idx & 15;
        stg[f][rest >> 1][(rest & 1) ? 17 : 0] = 0u;
    }
    __syncthreads();

    // ---- per-word ball-dilation counting (2 features x 2 rows x 16 words) ----
    float num = 0.0f;
    float den = 0.0f;

    if (c < 64) {
        const int f = c >> 5;            // dilated (source) feature
        const int rloc = (c >> 4) & 1;   // 0..1
        const int w = c & 15;
        const int gr = gb + rloc;

        unsigned a0c0, a0c1, a0c2, a0c3;
        unsigned a1c0 = 0, a1c1 = 0, a1c2 = 0, a1c3 = 0;
        unsigned a2c0 = 0, a2c1 = 0, a2c2 = 0;
        unsigned a3c0 = 0, a3c1 = 0;

        #pragma unroll
        for (int dr = -3; dr <= 3; ++dr) {
            const unsigned* row = &stg[f][rloc + 3 + dr][0];
            unsigned lo = row[w], mi = row[w + 1], hi = row[w + 2];
            unsigned c0 = mi;
            unsigned c1 = __funnelshift_r(mi, hi, 1) | __funnelshift_l(lo, mi, 1);
            const int adr = (dr < 0) ? -dr : dr;
            if (adr == 0) {
                a0c0 = c0; a0c1 = c1;
                a0c2 = __funnelshift_r(mi, hi, 2) | __funnelshift_l(lo, mi, 2);
                a0c3 = __funnelshift_r(mi, hi, 3) | __funnelshift_l(lo, mi, 3);
            } else if (adr == 1) {
                a1c0 |= c0; a1c1 |= c1;
                a1c2 |= __funnelshift_r(mi, hi, 2) | __funnelshift_l(lo, mi, 2);
                a1c3 |= __funnelshift_r(mi, hi, 3) | __funnelshift_l(lo, mi, 3);
            } else if (adr == 2) {
                a2c0 |= c0; a2c1 |= c1;
                a2c2 |= __funnelshift_r(mi, hi, 2) | __funnelshift_l(lo, mi, 2);
            } else {
                a3c0 |= c0; a3c1 |= c1;
            }
        }

        const unsigned tgt = stg[f ^ 1][rloc + 3][w + 1];
        den = (float)__popc(tgt);

        // incremental ball dilations: d^2 = 0,1,2,4,5,8,9,10
        unsigned D = a0c0, Dn;
        Dn = D | a0c1 | a1c0; num += 1.0f        * (float)__popc(tgt & Dn & ~D); D = Dn;
        Dn = D | a1c1;        num += 1.41421356f * (float)__popc(tgt & Dn & ~D); D = Dn;
        Dn = D | a0c2 | a2c0; num += 2.0f        * (float)__popc(tgt & Dn & ~D); D = Dn;
        Dn = D | a1c2 | a2c1; num += 2.23606798f * (float)__popc(tgt & Dn & ~D); D = Dn;
        Dn = D | a2c2;        num += 2.82842712f * (float)__popc(tgt & Dn & ~D); D = Dn;
        Dn = D | a0c3 | a3c0; num += 3.0f        * (float)__popc(tgt & Dn & ~D); D = Dn;
        Dn = D | a1c3 | a3c1; num += 3.16227766f * (float)__popc(tgt & Dn & ~D); D = Dn;

        // cold exact fallback (recomputes masks straight from float inputs)
        unsigned rem = tgt & ~D;
        while (rem) {
            int bt = __ffs(rem) - 1;
            rem &= rem - 1u;
            num += search_fb(f ? gt : pred, gr, w, bt);
        }
    }

    // ---- deterministic reduction + last-block fold ----
    #pragma unroll
    for (int off = 16; off > 0; off >>= 1) {
        num += __shfl_down_sync(0xFFFFFFFFu, num, off);
        den += __shfl_down_sync(0xFFFFFFFFu, den, off);
    }
    if (lane == 0) { wNum[wwarp] = num; wDen[wwarp] = den; }
    __syncthreads();

    if (wwarp == 0) {
        // only warps 0,1 ever hold nonzero partials, but fold all 16 for safety
        float n = (lane < 16) ? wNum[lane] : 0.0f;
        float d = (lane < 16) ? wDen[lane] : 0.0f;
        #pragma unroll
        for (int off = 8; off > 0; off >>= 1) {
            n += __shfl_down_sync(0xFFFFFFFFu, n, off);
            d += __shfl_down_sync(0xFFFFFFFFu, d, off);
        }
        if (lane == 0) {
            d_blkNum[blockIdx.x] = n;
            d_blkDen[blockIdx.x] = d;
            __threadfence();
            unsigned old = atomicInc(&d_cnt, GRID - 1);  // wraps -> self-reset
            isLast = (old == GRID - 1);
        }
    }
    __syncthreads();

    if (isLast) {
        float n = (c < GRID) ? d_blkNum[c] : 0.0f;
        float d = (c < GRID) ? d_blkDen[c] : 0.0f;
        #pragma unroll
        for (int off = 16; off > 0; off >>= 1) {
            n += __shfl_down_sync(0xFFFFFFFFu, n, off);
            d += __shfl_down_sync(0xFFFFFFFFu, d, off);
        }
        if (lane == 0) { wNum[wwarp] = n; wDen[wwarp] = d; }
        __syncthreads();
        if (wwarp == 0) {
            float nn = (lane < 16) ? wNum[lane] : 0.0f;
            float dd = (lane < 16) ? wDen[lane] : 0.0f;
            #pragma unroll
            for (int off = 8; off > 0; off >>= 1) {
                nn += __shfl_down_sync(0xFFFFFFFFu, nn, off);
                dd += __shfl_down_sync(0xFFFFFFFFu, dd, off);
            }
            if (lane == 0) out[0] = nn / dd;
        }
    }
}

extern "C" void kernel_launch(void* const* d_in, const int* in_sizes, int n_in,
                              void* d_out, int out_size) {
    const float* pred = (const float*)d_in[0];
    const float* gt   = (const float*)d_in[1];
    float* out = (float*)d_out;

    k_all<<<GRID, 512>>>(pred, gt, out);
}